// round 1
// baseline (speedup 1.0000x reference)
#include <cuda_runtime.h>
#include <cuda_bf16.h>

// SoftRankNDCGLoss: B=128, L=1024
// expected_ranks[b,i] = 1 + sum_{j!=i} ndtr((p_i - p_j)/sqrt(2))
//                     = 1 + (L-1)/2 + 0.5 * sum_j erf((p_i - p_j)/2)
// dcg[b]  = sum_i (2^t_i - 1) / log2(er_i + 1)
// idcg[b] = sum_r (2^{g_r} - 1) / log2(r + 2)   (grades sorted descending via counting sort)
// out     = -mean_b( dcg / (idcg + 1e-10) )

constexpr int BATCH = 128;
constexpr int LEN   = 1024;

__device__ float g_ndcg[BATCH];

__global__ __launch_bounds__(1024) void ndcg_row_kernel(
    const float* __restrict__ preds,
    const float* __restrict__ target)
{
    __shared__ float sp[LEN];
    __shared__ int   counts[8];
    __shared__ float red_dcg[32];
    __shared__ float red_idcg[32];

    const int b = blockIdx.x;
    const int i = threadIdx.x;

    const float pi = preds[b * LEN + i];
    sp[i] = pi;
    if (i < 8) counts[i] = 0;
    __syncthreads();

    const float ti = target[b * LEN + i];
    atomicAdd(&counts[(int)ti], 1);   // grades are 0..4

    // Pairwise erf sum over the full row (diagonal contributes erf(0)=0).
    float s = 0.0f;
    #pragma unroll 8
    for (int j = 0; j < LEN; ++j) {
        s += erff((pi - sp[j]) * 0.5f);
    }

    const float er     = 1.0f + 0.5f * (float)(LEN - 1) + 0.5f * s;
    const float gain   = exp2f(ti) - 1.0f;
    float dcg_i = gain / log2f(er + 1.0f);

    __syncthreads();  // counts complete

    // Counting-sort grade at descending rank i.
    int cum = counts[4];
    int gr  = 4;
    if (i >= cum) { cum += counts[3]; gr = 3; }
    if (i >= cum) { cum += counts[2]; gr = 2; }
    if (i >= cum) { cum += counts[1]; gr = 1; }
    if (i >= cum) { gr = 0; }

    float idcg_i = (exp2f((float)gr) - 1.0f) / log2f((float)(i + 2));

    // Deterministic block reduction (warp shuffle tree + cross-warp smem tree).
    const int lane = i & 31;
    const int warp = i >> 5;
    #pragma unroll
    for (int o = 16; o > 0; o >>= 1) {
        dcg_i  += __shfl_down_sync(0xFFFFFFFFu, dcg_i,  o);
        idcg_i += __shfl_down_sync(0xFFFFFFFFu, idcg_i, o);
    }
    if (lane == 0) { red_dcg[warp] = dcg_i; red_idcg[warp] = idcg_i; }
    __syncthreads();

    if (warp == 0) {
        float d  = red_dcg[lane];
        float id = red_idcg[lane];
        #pragma unroll
        for (int o = 16; o > 0; o >>= 1) {
            d  += __shfl_down_sync(0xFFFFFFFFu, d,  o);
            id += __shfl_down_sync(0xFFFFFFFFu, id, o);
        }
        if (lane == 0) {
            g_ndcg[b] = d / (id + 1e-10f);
        }
    }
}

__global__ void finalize_kernel(float* __restrict__ out)
{
    // 1 block, 128 threads; deterministic tree reduction over batch.
    __shared__ float red[4];
    const int t    = threadIdx.x;
    const int lane = t & 31;
    const int warp = t >> 5;

    float v = g_ndcg[t];
    #pragma unroll
    for (int o = 16; o > 0; o >>= 1)
        v += __shfl_down_sync(0xFFFFFFFFu, v, o);
    if (lane == 0) red[warp] = v;
    __syncthreads();

    if (t == 0) {
        float s = red[0] + red[1] + red[2] + red[3];
        out[0] = -s / (float)BATCH;
    }
}

extern "C" void kernel_launch(void* const* d_in, const int* in_sizes, int n_in,
                              void* d_out, int out_size)
{
    const float* preds  = (const float*)d_in[0];
    const float* target = (const float*)d_in[1];
    float* out = (float*)d_out;

    ndcg_row_kernel<<<BATCH, LEN>>>(preds, target);
    finalize_kernel<<<1, BATCH>>>(out);
}

// round 2
// speedup vs baseline: 2.9137x; 2.9137x over previous
#include <cuda_runtime.h>
#include <cuda_bf16.h>

// SoftRankNDCGLoss: B=128, L=1024
// er[b,i] = 1 + (L-1)/2 + 0.5 * sum_j tanh(A*d + B*d^3),  d = p_i - p_j
//   (tanh-cubic approximation of erf((p_i-p_j)/2); diagonal term is 0)
// dcg[b]  = sum_i (2^t_i - 1)/log2(er_i + 1)
// idcg[b] = counting-sort-based ideal DCG
// out     = -mean_b( dcg / (idcg + 1e-10) )

constexpr int BATCH = 128;
constexpr int LEN   = 1024;
constexpr int SPLIT = 8;              // CTAs per row
constexpr int TPB   = LEN / SPLIT;    // 128 threads per CTA

__device__ float g_dcg_part[BATCH][SPLIT];
__device__ float g_idcg[BATCH];

__device__ __forceinline__ unsigned long long pack2(float lo, float hi) {
    unsigned long long r;
    asm("mov.b64 %0, {%1, %2};" : "=l"(r) : "f"(lo), "f"(hi));
    return r;
}
__device__ __forceinline__ void unpack2(unsigned long long v, float& lo, float& hi) {
    asm("mov.b64 {%0, %1}, %2;" : "=f"(lo), "=f"(hi) : "l"(v));
}
__device__ __forceinline__ unsigned long long add2(unsigned long long a, unsigned long long b) {
    unsigned long long r;
    asm("add.rn.f32x2 %0, %1, %2;" : "=l"(r) : "l"(a), "l"(b));
    return r;
}
__device__ __forceinline__ unsigned long long mul2(unsigned long long a, unsigned long long b) {
    unsigned long long r;
    asm("mul.rn.f32x2 %0, %1, %2;" : "=l"(r) : "l"(a), "l"(b));
    return r;
}
__device__ __forceinline__ unsigned long long fma2(unsigned long long a, unsigned long long b,
                                                   unsigned long long c) {
    unsigned long long r;
    asm("fma.rn.f32x2 %0, %1, %2, %3;" : "=l"(r) : "l"(a), "l"(b), "l"(c));
    return r;
}
__device__ __forceinline__ float tanh_fast(float x) {
    float r;
    asm("tanh.approx.f32 %0, %1;" : "=f"(r) : "f"(x));
    return r;
}

__global__ __launch_bounds__(TPB, 7) void ndcg_main_kernel(
    const float* __restrict__ preds,
    const float* __restrict__ target)
{
    __shared__ __align__(16) float sn[LEN];   // negated preds row
    __shared__ int   counts[8];
    __shared__ float red[8];

    const int b   = blockIdx.x >> 3;          // row
    const int c   = blockIdx.x & 7;           // chunk within row
    const int tid = threadIdx.x;
    const int i   = c * TPB + tid;

    // Stage negated preds row into smem (8 elements per thread).
    const float* prow = preds + b * LEN;
    #pragma unroll
    for (int k = 0; k < SPLIT; ++k) {
        int idx = k * TPB + tid;
        sn[idx] = -prow[idx];
    }

    const float pi = prow[i];
    const float ti = target[b * LEN + i];

    // Chunk 0 additionally counts grades for the ideal sort.
    if (c == 0) {
        if (tid < 8) counts[tid] = 0;
        __syncthreads();   // counts zeroed before atomics (sn not read yet)
        const float* trow = target + b * LEN;
        #pragma unroll
        for (int k = 0; k < SPLIT; ++k) {
            atomicAdd(&counts[(int)trow[k * TPB + tid]], 1);
        }
    }
    __syncthreads();  // sn staged (+ counts complete for c==0)

    // Pairwise tanh-cubic sum: t = A*d + B*d^3, packed f32x2, HW tanh.
    const float A = 0.5641896f;
    const float B = 0.0126140f;
    const unsigned long long pi2 = pack2(pi, pi);
    const unsigned long long A2  = pack2(A, A);
    const unsigned long long B2  = pack2(B, B);
    const unsigned long long* sn2 = reinterpret_cast<const unsigned long long*>(sn);

    float s0 = 0.0f, s1 = 0.0f;
    #pragma unroll 4
    for (int j = 0; j < LEN / 2; ++j) {
        unsigned long long v  = sn2[j];          // LDS.64 broadcast
        unsigned long long d  = add2(pi2, v);    // d = pi - p_j (pairwise)
        unsigned long long dd = mul2(d, d);
        unsigned long long u  = fma2(dd, B2, A2);
        unsigned long long t  = mul2(d, u);
        float t0, t1;
        unpack2(t, t0, t1);
        s0 += tanh_fast(t0);
        s1 += tanh_fast(t1);
    }
    const float s = s0 + s1;

    const float er   = 1.0f + 0.5f * (float)(LEN - 1) + 0.5f * s;
    const float gain = exp2f(ti) - 1.0f;
    float dcg_i = gain / log2f(er + 1.0f);

    // Block reduction of dcg (4 warps).
    const int lane = tid & 31;
    const int warp = tid >> 5;
    #pragma unroll
    for (int o = 16; o > 0; o >>= 1)
        dcg_i += __shfl_down_sync(0xFFFFFFFFu, dcg_i, o);
    if (lane == 0) red[warp] = dcg_i;
    __syncthreads();
    if (tid == 0) {
        g_dcg_part[b][c] = red[0] + red[1] + red[2] + red[3];
    }

    // Chunk 0 computes idcg for the whole row (cheap).
    if (c == 0) {
        const int c4 = counts[4];
        const int c3 = c4 + counts[3];
        const int c2 = c3 + counts[2];
        const int c1 = c2 + counts[1];
        float idcg_i = 0.0f;
        #pragma unroll
        for (int k = 0; k < SPLIT; ++k) {
            int r = k * TPB + tid;          // descending rank
            int g = (r < c4) ? 4 : (r < c3) ? 3 : (r < c2) ? 2 : (r < c1) ? 1 : 0;
            float gn = (float)((1 << g) - 1);
            idcg_i += gn / log2f((float)(r + 2));
        }
        #pragma unroll
        for (int o = 16; o > 0; o >>= 1)
            idcg_i += __shfl_down_sync(0xFFFFFFFFu, idcg_i, o);
        __syncthreads();     // red[] reuse safe
        if (lane == 0) red[4 + warp] = idcg_i;
        __syncthreads();
        if (tid == 0) {
            g_idcg[b] = red[4] + red[5] + red[6] + red[7];
        }
    }
}

__global__ void finalize_kernel(float* __restrict__ out)
{
    __shared__ float red[4];
    const int t    = threadIdx.x;
    const int lane = t & 31;
    const int warp = t >> 5;

    float d = 0.0f;
    #pragma unroll
    for (int c = 0; c < SPLIT; ++c) d += g_dcg_part[t][c];
    float v = d / (g_idcg[t] + 1e-10f);

    #pragma unroll
    for (int o = 16; o > 0; o >>= 1)
        v += __shfl_down_sync(0xFFFFFFFFu, v, o);
    if (lane == 0) red[warp] = v;
    __syncthreads();

    if (t == 0) {
        float s = red[0] + red[1] + red[2] + red[3];
        out[0] = -s / (float)BATCH;
    }
}

extern "C" void kernel_launch(void* const* d_in, const int* in_sizes, int n_in,
                              void* d_out, int out_size)
{
    const float* preds  = (const float*)d_in[0];
    const float* target = (const float*)d_in[1];
    float* out = (float*)d_out;

    ndcg_main_kernel<<<BATCH * SPLIT, TPB>>>(preds, target);
    finalize_kernel<<<1, BATCH>>>(out);
}

// round 3
// speedup vs baseline: 9.7862x; 3.3587x over previous
#include <cuda_runtime.h>
#include <cuda_bf16.h>

// SoftRankNDCGLoss: B=128, L=1024
//
// s_i = sum_j erf((p_i - p_j)/2) = f(p_i), f(x) = sum_j erf((x - p_j)/2).
// f is Gaussian-smoothed (kernel width sqrt(2)) -> build f on an adaptive
// M-point grid per row (tanh-cubic approx of erf, HW tanh, packed f32x2),
// then cubic-interpolate f(p_i). 8x fewer transcendental evals than O(L^2).
//
// er_i  = 512.5 + 0.5*f(p_i)
// dcg   = sum_i (2^t_i - 1)/log2(er_i + 1)
// idcg  = counting-sort ideal DCG
// out   = -mean_b( dcg/(idcg + 1e-10) )   (fused last-block finalize)

constexpr int BATCH = 128;
constexpr int LEN   = 1024;
constexpr int M     = 128;    // grid points per row
constexpr int TPB   = 1024;

__device__ float g_ndcg[BATCH];
__device__ int   g_done = 0;

typedef unsigned long long ull;

__device__ __forceinline__ ull pack2(float lo, float hi) {
    ull r; asm("mov.b64 %0, {%1, %2};" : "=l"(r) : "f"(lo), "f"(hi)); return r;
}
__device__ __forceinline__ void unpack2(ull v, float& lo, float& hi) {
    asm("mov.b64 {%0, %1}, %2;" : "=f"(lo), "=f"(hi) : "l"(v));
}
__device__ __forceinline__ ull add2(ull a, ull b) {
    ull r; asm("add.rn.f32x2 %0, %1, %2;" : "=l"(r) : "l"(a), "l"(b)); return r;
}
__device__ __forceinline__ ull mul2(ull a, ull b) {
    ull r; asm("mul.rn.f32x2 %0, %1, %2;" : "=l"(r) : "l"(a), "l"(b)); return r;
}
__device__ __forceinline__ ull fma2(ull a, ull b, ull c) {
    ull r; asm("fma.rn.f32x2 %0, %1, %2, %3;" : "=l"(r) : "l"(a), "l"(b), "l"(c)); return r;
}
__device__ __forceinline__ float tanh_fast(float x) {
    float r; asm("tanh.approx.f32 %0, %1;" : "=f"(r) : "f"(x)); return r;
}

__global__ __launch_bounds__(TPB, 1) void ndcg_kernel(
    const float* __restrict__ preds,
    const float* __restrict__ target,
    float* __restrict__ out)
{
    __shared__ __align__(16) float sn[LEN];        // negated preds row
    __shared__ float spart[8][M];                  // grid partials
    __shared__ float sg[M];                        // grid f values
    __shared__ float sred[64];
    __shared__ float s_lo, s_hi;
    __shared__ int   scnt[5];
    __shared__ int   slast;

    const int b    = blockIdx.x;
    const int tid  = threadIdx.x;
    const int lane = tid & 31;
    const int warp = tid >> 5;

    const float pi = preds[b * LEN + tid];
    const float ti = target[b * LEN + tid];
    sn[tid] = -pi;
    if (tid < 5) scnt[tid] = 0;
    if (tid == 0) slast = 0;

    // ---- row min/max: warp reduce -> smem ----
    float mn = pi, mx = pi;
    #pragma unroll
    for (int o = 16; o > 0; o >>= 1) {
        mn = fminf(mn, __shfl_down_sync(0xFFFFFFFFu, mn, o));
        mx = fmaxf(mx, __shfl_down_sync(0xFFFFFFFFu, mx, o));
    }
    if (lane == 0) { sred[warp] = mn; sred[32 + warp] = mx; }
    __syncthreads();   // sn staged, scnt zeroed, partial min/max in sred

    // ---- grade counting via warp ballots (no per-thread atomics) ----
    const int gi = (int)ti;
    #pragma unroll
    for (int gr = 0; gr < 5; ++gr) {
        unsigned bl = __ballot_sync(0xFFFFFFFFu, gi == gr);
        if (lane == 0) atomicAdd(&scnt[gr], __popc(bl));
    }
    // warp 0 finishes min/max
    if (warp == 0) {
        float a = sred[lane], c = sred[32 + lane];
        #pragma unroll
        for (int o = 16; o > 0; o >>= 1) {
            a = fminf(a, __shfl_down_sync(0xFFFFFFFFu, a, o));
            c = fmaxf(c, __shfl_down_sync(0xFFFFFFFFu, c, o));
        }
        if (lane == 0) { s_lo = a; s_hi = c; }
    }
    __syncthreads();

    const float lo   = s_lo;
    const float span = fmaxf(s_hi - lo, 1e-3f);
    const float h    = span / (float)(M - 4);
    const float invh = (float)(M - 4) / span;

    // ---- build f on the grid: point m_pt, j-chunk sub ----
    // All lanes in a warp share sub -> smem loads are pure broadcast.
    const int m_pt = tid & (M - 1);
    const int sub  = tid >> 7;                     // 0..7
    const float x  = lo + ((float)m_pt - 1.5f) * h;

    const float A = 0.5641896f;
    const float B = 0.0126140f;
    const ull x2 = pack2(x, x);
    const ull A2 = pack2(A, A);
    const ull B2 = pack2(B, B);
    const ull* sn2 = reinterpret_cast<const ull*>(sn);

    float s0 = 0.0f, s1 = 0.0f;
    const int base = sub * 64;                     // 64 x f32x2 = 128 elems
    #pragma unroll 4
    for (int jj = 0; jj < 64; ++jj) {
        ull v  = sn2[base + jj];
        ull d  = add2(x2, v);                      // x - p_j (pairwise)
        ull dd = mul2(d, d);
        ull u  = fma2(dd, B2, A2);
        ull t  = mul2(d, u);
        float t0, t1; unpack2(t, t0, t1);
        s0 += tanh_fast(t0);
        s1 += tanh_fast(t1);
    }
    spart[sub][m_pt] = s0 + s1;
    __syncthreads();

    if (tid < M) {
        float g = spart[0][tid];
        #pragma unroll
        for (int s = 1; s < 8; ++s) g += spart[s][tid];
        sg[tid] = g;
    }
    __syncthreads();

    // ---- cubic Lagrange interpolation of f at p_i ----
    const float u  = (pi - lo) * invh + 1.5f;
    int m = (int)floorf(u);
    m = min(max(m, 1), M - 3);
    const float tf = u - (float)m;
    const float ta = tf - 1.0f;
    const float tb = tf - 2.0f;
    const float tc = tf + 1.0f;
    const float wm1 = -tf * ta * tb * (1.0f / 6.0f);
    const float w0  =  tc * ta * tb * 0.5f;
    const float w1  = -tc * tf * tb * 0.5f;
    const float w2  =  tc * tf * ta * (1.0f / 6.0f);
    const float f = wm1 * sg[m - 1] + w0 * sg[m] + w1 * sg[m + 1] + w2 * sg[m + 2];

    const float er   = 512.5f + 0.5f * f;          // 1 + (L-1)/2 + 0.5*f
    const float gain = exp2f(ti) - 1.0f;
    float dcg_i = gain / log2f(er + 1.0f);

    // ---- ideal DCG term at descending rank tid ----
    const int c4 = scnt[4];
    const int c3 = c4 + scnt[3];
    const int c2 = c3 + scnt[2];
    const int c1 = c2 + scnt[1];
    const int gr = (tid < c4) ? 4 : (tid < c3) ? 3 : (tid < c2) ? 2 : (tid < c1) ? 1 : 0;
    float idcg_i = (float)((1 << gr) - 1) / log2f((float)(tid + 2));

    // ---- block reduction (dcg, idcg together) ----
    #pragma unroll
    for (int o = 16; o > 0; o >>= 1) {
        dcg_i  += __shfl_down_sync(0xFFFFFFFFu, dcg_i,  o);
        idcg_i += __shfl_down_sync(0xFFFFFFFFu, idcg_i, o);
    }
    __syncthreads();   // sred reuse safe
    if (lane == 0) { sred[warp] = dcg_i; sred[32 + warp] = idcg_i; }
    __syncthreads();

    if (warp == 0) {
        float d  = sred[lane];
        float id = sred[32 + lane];
        #pragma unroll
        for (int o = 16; o > 0; o >>= 1) {
            d  += __shfl_down_sync(0xFFFFFFFFu, d,  o);
            id += __shfl_down_sync(0xFFFFFFFFu, id, o);
        }
        if (lane == 0) {
            g_ndcg[b] = d / (id + 1e-10f);
            __threadfence();
            int old = atomicAdd(&g_done, 1);
            slast = (old == gridDim.x - 1);
        }
    }
    __syncthreads();

    // ---- fused finalize: last CTA computes the mean ----
    if (slast) {
        if (tid < BATCH) {
            float v = g_ndcg[tid];
            #pragma unroll
            for (int o = 16; o > 0; o >>= 1)
                v += __shfl_down_sync(0xFFFFFFFFu, v, o);
            if (lane == 0) sred[warp] = v;
        }
        __syncthreads();
        if (tid == 0) {
            float s = sred[0] + sred[1] + sred[2] + sred[3];
            out[0] = -s / (float)BATCH;
            g_done = 0;                 // reset for next graph replay
        }
    }
}

extern "C" void kernel_launch(void* const* d_in, const int* in_sizes, int n_in,
                              void* d_out, int out_size)
{
    const float* preds  = (const float*)d_in[0];
    const float* target = (const float*)d_in[1];
    float* out = (float*)d_out;

    ndcg_kernel<<<BATCH, TPB>>>(preds, target, out);
}

// round 5
// speedup vs baseline: 11.8542x; 1.2113x over previous
#include <cuda_runtime.h>
#include <cuda_bf16.h>

// SoftRankNDCGLoss: B=128, L=1024
//
// s_i = f(p_i), f(x) = sum_j erf((x - p_j)/2)  (Gaussian-smoothed ECDF).
// Build f on an adaptive M=64 grid per row (tanh-cubic erf approx, HW tanh,
// packed f32x2), cubic-interpolate f at each p_i.
// er_i = 512.5 + 0.5*f(p_i); dcg = sum (2^t-1)/log2(er+1); idcg via counting
// sort; out = -mean_b(dcg/(idcg+1e-10)), fused last-block finalize.

constexpr int BATCH = 128;
constexpr int LEN   = 1024;
constexpr int M     = 64;               // grid points per row
constexpr int SUBS  = LEN / M;          // 16 j-chunks
constexpr int TPB   = 1024;

__device__ float g_ndcg[BATCH];
__device__ int   g_done = 0;

typedef unsigned long long ull;

__device__ __forceinline__ ull pack2(float lo, float hi) {
    ull r; asm("mov.b64 %0, {%1, %2};" : "=l"(r) : "f"(lo), "f"(hi)); return r;
}
__device__ __forceinline__ void unpack2(ull v, float& lo, float& hi) {
    asm("mov.b64 {%0, %1}, %2;" : "=f"(lo), "=f"(hi) : "l"(v));
}
__device__ __forceinline__ ull add2(ull a, ull b) {
    ull r; asm("add.rn.f32x2 %0, %1, %2;" : "=l"(r) : "l"(a), "l"(b)); return r;
}
__device__ __forceinline__ ull mul2(ull a, ull b) {
    ull r; asm("mul.rn.f32x2 %0, %1, %2;" : "=l"(r) : "l"(a), "l"(b)); return r;
}
__device__ __forceinline__ ull fma2(ull a, ull b, ull c) {
    ull r; asm("fma.rn.f32x2 %0, %1, %2, %3;" : "=l"(r) : "l"(a), "l"(b), "l"(c)); return r;
}
__device__ __forceinline__ float tanh_fast(float x) {
    float r; asm("tanh.approx.f32 %0, %1;" : "=f"(r) : "f"(x)); return r;
}
__device__ __forceinline__ float warp_sum(float v) {
    #pragma unroll
    for (int o = 16; o > 0; o >>= 1)
        v += __shfl_down_sync(0xFFFFFFFFu, v, o);
    return v;
}

__global__ __launch_bounds__(TPB, 1) void ndcg_kernel(
    const float* __restrict__ preds,
    const float* __restrict__ target,
    float* __restrict__ out)
{
    __shared__ __align__(16) float sn[LEN];        // negated preds row
    __shared__ float spart[SUBS][M];               // grid partials
    __shared__ float sg[M];                        // grid f values
    __shared__ float sred[64];
    __shared__ float s_lo, s_hi;
    __shared__ int   scnt[5];
    __shared__ int   slast;

    const int b    = blockIdx.x;
    const int tid  = threadIdx.x;
    const int lane = tid & 31;
    const int warp = tid >> 5;

    const float pi = preds[b * LEN + tid];
    const float ti = target[b * LEN + tid];
    sn[tid] = -pi;
    if (tid < 5) scnt[tid] = 0;
    if (tid == 0) slast = 0;

    // ---- row min/max (shuffle tree -> smem -> warp0 tree) ----
    float mn = pi, mx = pi;
    #pragma unroll
    for (int o = 16; o > 0; o >>= 1) {
        mn = fminf(mn, __shfl_down_sync(0xFFFFFFFFu, mn, o));
        mx = fmaxf(mx, __shfl_down_sync(0xFFFFFFFFu, mx, o));
    }
    if (lane == 0) { sred[warp] = mn; sred[32 + warp] = mx; }
    __syncthreads();   // sn staged, scnt zeroed, partial min/max in sred

    // ---- grade counting via warp ballots ----
    const int gi = (int)ti;
    #pragma unroll
    for (int gr = 0; gr < 5; ++gr) {
        unsigned bl = __ballot_sync(0xFFFFFFFFu, gi == gr);
        if (lane == 0) atomicAdd(&scnt[gr], __popc(bl));
    }
    if (warp == 0) {
        float a = sred[lane], c = sred[32 + lane];
        #pragma unroll
        for (int o = 16; o > 0; o >>= 1) {
            a = fminf(a, __shfl_down_sync(0xFFFFFFFFu, a, o));
            c = fmaxf(c, __shfl_down_sync(0xFFFFFFFFu, c, o));
        }
        if (lane == 0) { s_lo = a; s_hi = c; }
    }
    __syncthreads();

    const float lo   = s_lo;
    const float span = fmaxf(s_hi - lo, 1e-3f);
    const float h    = span / (float)(M - 4);
    const float invh = (float)(M - 4) / span;

    // ---- build f on the grid: point m_pt, j-chunk sub ----
    const int m_pt = tid & (M - 1);
    const int sub  = tid >> 6;                     // 0..15
    const float x  = lo + ((float)m_pt - 1.5f) * h;

    const float A = 0.5641896f;
    const float B = 0.0126140f;
    const ull x2 = pack2(x, x);
    const ull A2 = pack2(A, A);
    const ull B2 = pack2(B, B);
    const ull* sn2 = reinterpret_cast<const ull*>(sn);

    float s0 = 0.0f, s1 = 0.0f;
    const int base = sub * (M / 2);                // 32 x f32x2 = 64 elems
    #pragma unroll 8
    for (int jj = 0; jj < M / 2; ++jj) {
        ull v  = sn2[base + jj];                   // LDS.64 broadcast
        ull d  = add2(x2, v);                      // x - p_j (pairwise)
        ull dd = mul2(d, d);
        ull u  = fma2(dd, B2, A2);
        ull t  = mul2(d, u);
        float t0, t1; unpack2(t, t0, t1);
        s0 += tanh_fast(t0);
        s1 += tanh_fast(t1);
    }
    spart[sub][m_pt] = s0 + s1;
    __syncthreads();

    if (tid < M) {
        float g = spart[0][tid];
        #pragma unroll
        for (int s = 1; s < SUBS; ++s) g += spart[s][tid];
        sg[tid] = g;
    }
    __syncthreads();

    // ---- cubic Lagrange interpolation of f at p_i ----
    const float u  = (pi - lo) * invh + 1.5f;
    int m = (int)floorf(u);
    m = min(max(m, 1), M - 3);
    const float tf = u - (float)m;
    const float ta = tf - 1.0f;
    const float tb = tf - 2.0f;
    const float tc = tf + 1.0f;
    const float wm1 = -tf * ta * tb * (1.0f / 6.0f);
    const float w0  =  tc * ta * tb * 0.5f;
    const float w1  = -tc * tf * tb * 0.5f;
    const float w2  =  tc * tf * ta * (1.0f / 6.0f);
    const float f = wm1 * sg[m - 1] + w0 * sg[m] + w1 * sg[m + 1] + w2 * sg[m + 2];

    const float er   = 512.5f + 0.5f * f;          // 1 + (L-1)/2 + 0.5*f
    const float gain = (float)((1 << gi) - 1);     // grades are integer 0..4
    float dcg_i = __fdividef(gain, __log2f(er + 1.0f));

    // ---- ideal DCG term at descending rank tid ----
    const int c4 = scnt[4];
    const int c3 = c4 + scnt[3];
    const int c2 = c3 + scnt[2];
    const int c1 = c2 + scnt[1];
    const int gr = (tid < c4) ? 4 : (tid < c3) ? 3 : (tid < c2) ? 2 : (tid < c1) ? 1 : 0;
    float idcg_i = __fdividef((float)((1 << gr) - 1), __log2f((float)(tid + 2)));

    // ---- block reduction (dcg, idcg together) ----
    #pragma unroll
    for (int o = 16; o > 0; o >>= 1) {
        dcg_i  += __shfl_down_sync(0xFFFFFFFFu, dcg_i,  o);
        idcg_i += __shfl_down_sync(0xFFFFFFFFu, idcg_i, o);
    }
    __syncthreads();   // sred reuse safe
    if (lane == 0) { sred[warp] = dcg_i; sred[32 + warp] = idcg_i; }
    __syncthreads();

    if (warp == 0) {
        float d  = sred[lane];
        float id = sred[32 + lane];
        #pragma unroll
        for (int o = 16; o > 0; o >>= 1) {
            d  += __shfl_down_sync(0xFFFFFFFFu, d,  o);
            id += __shfl_down_sync(0xFFFFFFFFu, id, o);
        }
        if (lane == 0) {
            g_ndcg[b] = d / (id + 1e-10f);
            __threadfence();
            int old = atomicAdd(&g_done, 1);
            slast = (old == gridDim.x - 1);
        }
    }
    __syncthreads();

    // ---- fused finalize: last CTA computes the mean ----
    if (slast) {
        if (tid < BATCH) {
            float v = warp_sum(g_ndcg[tid]);
            if (lane == 0) sred[warp] = v;
        }
        __syncthreads();
        if (tid == 0) {
            float s = sred[0] + sred[1] + sred[2] + sred[3];
            out[0] = -s / (float)BATCH;
            g_done = 0;                 // reset for next graph replay
        }
    }
}

extern "C" void kernel_launch(void* const* d_in, const int* in_sizes, int n_in,
                              void* d_out, int out_size)
{
    const float* preds  = (const float*)d_in[0];
    const float* target = (const float*)d_in[1];
    float* out = (float*)d_out;

    ndcg_kernel<<<BATCH, TPB>>>(preds, target, out);
}